// round 17
// baseline (speedup 1.0000x reference)
#include <cuda_runtime.h>

#define BB 2
#define NQv 1024
#define NKv 1024
#define DD 512
#define HH 32

// Scratch (no cudaMalloc allowed). Raw f32 projections.
__device__ __align__(16) float g_hk[BB * NKv * HH];   // keys@W1[:D] + b1
__device__ __align__(16) float g_hq[BB * NQv * HH];   // queries@W1[D:]

__device__ __forceinline__ float tanh_fast(float x) {
    float y; asm("tanh.approx.f32 %0, %1;" : "=f"(y) : "f"(x)); return y;
}
__device__ __forceinline__ unsigned smem_u32(const void* p) {
    return (unsigned)__cvta_generic_to_shared(p);
}
__device__ __forceinline__ void cp16(unsigned dst, const void* src) {
    asm volatile("cp.async.cg.shared.global [%0], [%1], 16;" :: "r"(dst), "l"(src));
}
__device__ __forceinline__ void cp_commit() {
    asm volatile("cp.async.commit_group;");
}
template <int N> __device__ __forceinline__ void cp_wait() {
    asm volatile("cp.async.wait_group %0;" :: "n"(N));
}

// ---------------------------------------------------------------------------
// Projection v12 (cp.async double buffer + 2x occupancy):
// C[2048,32] = A[2048,512]@W[512,32] per tensor. Grid (128,2) = 256 blocks
// (~1.7/SM co-resident; smem 16 KB allows 2-3 blocks/SM), 256 thr, 16
// rows/block, thread = 2 rows x 1 h, K in 8 chunks of 64 d.
// Protocol per chunk (verified R13/R16 ordering): stage(c+1) -> commit ->
// wait(c, per-thread) -> __syncthreads (cross-thread publish) -> compute(c)
// -> __syncthreads (WAR). Do not reorder: the barrier AFTER the wait is
// what makes other threads' cp.async data visible.
// ---------------------------------------------------------------------------
__global__ __launch_bounds__(256) void proj_kernel(
    const float* __restrict__ keys, const float* __restrict__ queries,
    const float* __restrict__ W1, const float* __restrict__ b1)
{
    __shared__ __align__(16) float as[2][16][64];   // A chunks (2 x 4 KB)
    __shared__ __align__(16) float ws[2][64][32];   // W chunks (2 x 8 KB)

    const int z    = blockIdx.y;
    const int tid  = threadIdx.x;
    const int h    = tid & 31;
    const int warp = tid >> 5;
    const int row0 = blockIdx.x * 16;
    const float* __restrict__ src = z ? queries : keys;

    // Per-thread staging geometry (constant across chunks).
    const int ar  = tid >> 4,         aj  = tid & 15;   // A: 1 item/thread
    const int wd0 = tid >> 3,         wj0 = tid & 7;    // W item 0
    const int wd1 = (tid + 256) >> 3, wj1 = tid & 7;    // W item 1
    const float4* __restrict__ ag = (const float4*)src;
    const float4* __restrict__ wg =
        (const float4*)(W1 + (size_t)(z * DD) * HH);

    auto stage = [&](int c, int buf) {
        cp16(smem_u32(&as[buf][ar][aj * 4]),
             ag + (size_t)(row0 + ar) * (DD / 4) + c * 16 + aj);
        cp16(smem_u32(&ws[buf][wd0][wj0 * 4]), wg + (size_t)c * 512 + tid);
        cp16(smem_u32(&ws[buf][wd1][wj1 * 4]), wg + (size_t)c * 512 + tid + 256);
    };

    float acc0 = 0.f, acc1 = 0.f;

    stage(0, 0);
    cp_commit();

    #pragma unroll
    for (int c = 0; c < 8; ++c) {
        const int buf = c & 1;
        if (c < 7) {
            stage(c + 1, buf ^ 1);
            cp_commit();
            cp_wait<1>();       // chunk c complete (per-thread)
        } else {
            cp_wait<0>();
        }
        __syncthreads();        // publish: all threads' chunk-c data visible

        #pragma unroll
        for (int d4 = 0; d4 < 16; ++d4) {
            const float4 a0 = *(const float4*)&as[buf][2 * warp + 0][d4 * 4];
            const float4 a1 = *(const float4*)&as[buf][2 * warp + 1][d4 * 4];
            const float w0  = ws[buf][d4 * 4 + 0][h];
            const float w1v = ws[buf][d4 * 4 + 1][h];
            const float w2v = ws[buf][d4 * 4 + 2][h];
            const float w3v = ws[buf][d4 * 4 + 3][h];
            acc0 = fmaf(a0.x, w0, acc0);  acc1 = fmaf(a1.x, w0, acc1);
            acc0 = fmaf(a0.y, w1v, acc0); acc1 = fmaf(a1.y, w1v, acc1);
            acc0 = fmaf(a0.z, w2v, acc0); acc1 = fmaf(a1.z, w2v, acc1);
            acc0 = fmaf(a0.w, w3v, acc0); acc1 = fmaf(a1.w, w3v, acc1);
        }
        __syncthreads();        // WAR: buffer free for chunk c+2's stage
    }

    const float bias = (z == 0) ? __ldg(&b1[h]) : 0.f;
    float* __restrict__ dst = (z == 0) ? g_hk : g_hq;
    const int r0 = row0 + 2 * warp;
    dst[(size_t)(r0 + 0) * HH + h] = acc0 + bias;
    dst[(size_t)(r0 + 1) * HH + h] = acc1 + bias;
}

// ---------------------------------------------------------------------------
// Scoring (best measured 20.35us config, R16 verbatim): 64q x 32k tile,
// 256 thr, thread = 4q x 2k, f32 tanh on XU pipe, bias-initialized accs.
// ---------------------------------------------------------------------------
__global__ __launch_bounds__(256) void score_kernel(
    const float* __restrict__ W2, const float* __restrict__ b2,
    float* __restrict__ out)
{
    __shared__ float hqs[64][32];
    __shared__ float hks[32][33];
    __shared__ float w2s[32];

    const int b   = blockIdx.z;
    const int q0  = blockIdx.y * 64;
    const int k0  = blockIdx.x * 32;
    const int tid = threadIdx.x;

    {
        const float4* __restrict__ hq_g =
            (const float4*)(g_hq + (size_t)(b * NQv + q0) * HH);
        float4* hqv = (float4*)&hqs[0][0];
        hqv[tid]       = hq_g[tid];
        hqv[tid + 256] = hq_g[tid + 256];
        const float* __restrict__ hk_g = g_hk + (size_t)(b * NKv + k0) * HH;
        #pragma unroll
        for (int it = 0; it < 4; ++it) {
            const int i = tid + it * 256;
            hks[i >> 5][i & 31] = hk_g[i];
        }
        if (tid < 32) w2s[tid] = __ldg(&W2[tid]);
    }
    const float bias = __ldg(b2);
    __syncthreads();

    const int kk = (tid & 15) * 2;
    const int qq = (tid >> 4) * 4;

    float a00 = bias, a01 = bias, a10 = bias, a11 = bias;
    float a20 = bias, a21 = bias, a30 = bias, a31 = bias;

    #pragma unroll
    for (int h = 0; h < HH; ++h) {
        const float w   = w2s[h];
        const float bk0 = hks[kk][h];
        const float bk1 = hks[kk + 1][h];
        const float q0v = hqs[qq + 0][h];
        const float q1v = hqs[qq + 1][h];
        const float q2v = hqs[qq + 2][h];
        const float q3v = hqs[qq + 3][h];
        a00 = fmaf(w, tanh_fast(q0v + bk0), a00);
        a01 = fmaf(w, tanh_fast(q0v + bk1), a01);
        a10 = fmaf(w, tanh_fast(q1v + bk0), a10);
        a11 = fmaf(w, tanh_fast(q1v + bk1), a11);
        a20 = fmaf(w, tanh_fast(q2v + bk0), a20);
        a21 = fmaf(w, tanh_fast(q2v + bk1), a21);
        a30 = fmaf(w, tanh_fast(q3v + bk0), a30);
        a31 = fmaf(w, tanh_fast(q3v + bk1), a31);
    }

    float* __restrict__ o =
        out + (size_t)(b * NQv + q0 + qq) * NKv + k0 + kk;
    *(float2*)(o + 0 * NKv) = make_float2(a00, a01);
    *(float2*)(o + 1 * NKv) = make_float2(a10, a11);
    *(float2*)(o + 2 * NKv) = make_float2(a20, a21);
    *(float2*)(o + 3 * NKv) = make_float2(a30, a31);
}

extern "C" void kernel_launch(void* const* d_in, const int* in_sizes, int n_in,
                              void* d_out, int out_size)
{
    const float* keys    = (const float*)d_in[0];
    const float* queries = (const float*)d_in[1];
    const float* W1      = (const float*)d_in[2];
    const float* b1      = (const float*)d_in[3];
    const float* W2      = (const float*)d_in[4];
    const float* b2      = (const float*)d_in[5];
    float* out = (float*)d_out;

    proj_kernel<<<dim3(128, 2, 1), 256>>>(keys, queries, W1, b1);
    score_kernel<<<dim3(NKv / 32, NQv / 64, BB), 256>>>(W2, b2, out);
}